// round 16
// baseline (speedup 1.0000x reference)
#include <cuda_runtime.h>
#include <cuda_fp16.h>
#include <cuda_fp8.h>
#include <cstdint>

#define IN_CH  512
#define HID    16
#define OUT_CH 64
#define MAX_NODES 100352
#define MAX_EDGES 3276800

// ---- scratch (device globals; no allocation allowed) ----
__device__ float   g_deg  [MAX_NODES];
__device__ float   g_dinv [MAX_NODES];
__device__ uint8_t g_h1q  [MAX_NODES * HID];  // e4m3 dinv-prescaled x@W1 (1.6MB, L2-resident)
__device__ uint8_t g_zq   [MAX_NODES * HID];  // e4m3 dinv*relu(dinv*agg1+b1)
__device__ __half  g_agg1h[MAX_NODES * HID];  // fp16 accumulation buffers
__device__ __half  g_agg2h[MAX_NODES * HID];

// 128-bit fp16x2 reduction: 8 halves in ONE red-lane-op
__device__ __forceinline__ void red_add_v4h2(__half* p, uint32_t r0, uint32_t r1,
                                             uint32_t r2, uint32_t r3) {
    asm volatile("red.global.add.noftz.v4.f16x2 [%0], {%1,%2,%3,%4};"
                 :: "l"(p), "r"(r0), "r"(r1), "r"(r2), "r"(r3) : "memory");
}

__device__ __forceinline__ void cp_async16(uint32_t dst, const void* src) {
    asm volatile("cp.async.cg.shared.global [%0], [%1], 16;" :: "r"(dst), "l"(src));
}

__device__ __forceinline__ uint32_t f2tf32(float f) {
    uint32_t r;
    asm("cvt.rna.tf32.f32 %0, %1;" : "=r"(r) : "f"(f));
    return r;
}

// fp8 helpers
__device__ __forceinline__ uint16_t f2_to_e4m3x2(float a, float b) {
    return (uint16_t)__nv_cvt_float2_to_fp8x2(make_float2(a, b), __NV_SATFINITE, __NV_E4M3);
}
__device__ __forceinline__ __half2 e4m3x2_to_h2(uint16_t v) {
    __half2_raw r = __nv_cvt_fp8x2_to_halfraw2((__nv_fp8x2_storage_t)v, __NV_E4M3);
    return *(__half2*)&r;
}

// D += A(16x8) * B(8x8), tf32 inputs, fp32 accum
__device__ __forceinline__ void mma_tf32(float* c, uint32_t a0, uint32_t a1,
                                         uint32_t a2, uint32_t a3,
                                         uint32_t b0, uint32_t b1) {
    asm volatile("mma.sync.aligned.m16n8k8.row.col.f32.tf32.tf32.f32 "
                 "{%0,%1,%2,%3}, {%4,%5,%6,%7}, {%8,%9}, {%0,%1,%2,%3};"
                 : "+f"(c[0]), "+f"(c[1]), "+f"(c[2]), "+f"(c[3])
                 : "r"(a0), "r"(a1), "r"(a2), "r"(a3), "r"(b0), "r"(b1));
}

// ---------------------------------------------------------------- zero (agg1h + deg)
__global__ void zero_kernel(int n) {
    int i = blockIdx.x * blockDim.x + threadIdx.x;
    int t4 = n * HID / 8;            // uint4 = 8 halves
    if (i < t4) ((uint4*)g_agg1h)[i] = make_uint4(0u, 0u, 0u, 0u);
    if (i < n) g_deg[i] = 0.f;
}

// ---------------------------------------------------------------- degree
__global__ void deg_kernel(const int* __restrict__ ei1, const float* __restrict__ w1, int E1,
                           const int* __restrict__ ei2, const float* __restrict__ w2, int E2) {
    int i = blockIdx.x * blockDim.x + threadIdx.x;
    if (i < E1) {
        atomicAdd(&g_deg[ei1[i]], w1[i]);
    } else {
        int j = i - E1;
        if (j < E2) atomicAdd(&g_deg[ei2[j]], w2[j]);
    }
}

__global__ void dinv_kernel(int n) {
    int i = blockIdx.x * blockDim.x + threadIdx.x;
    if (i >= n) return;
    float d = g_deg[i];
    g_dinv[i] = d > 0.f ? rsqrtf(fmaxf(d, 1e-12f)) : 0.f;
}

// ---------------------------------------------------------------- h1q = e4m3(dinv .* (x @ W1))  [tf32 tensor cores]
// R13 champion shape: warp = 16 nodes, 2 mma n-tiles, KC=32 floats/chunk,
// cp.async double-buffered, 64KB smem -> 3 blocks/SM. fp8 epilogue.
#define GM_THREADS 256
#define GM_WARPS   8
#define GM_NPW     16
#define GM_TILE    (GM_WARPS * GM_NPW)      // 128 nodes per block
#define GM_KC      32                       // floats per chunk
#define GM_NCHUNK  (IN_CH / GM_KC)          // 16
#define GM_BUF     (GM_NPW * GM_KC)         // 512 floats per buffer (2048 bytes)
#define GM_WF_FLOATS (64 * 2 * 32 * 2)      // 8192 floats = 32KB
#define GM_SMEM_FLOATS (GM_WF_FLOATS + GM_WARPS * 2 * GM_BUF)  // 64KB

__global__ void __launch_bounds__(GM_THREADS, 3)
gemm1_kernel(const float* __restrict__ x, const float* __restrict__ W1, int n) {
    extern __shared__ float smem[];
    float2* Wf = (float2*)smem;             // [ks(64)][tile(2)][lane(32)] -> (b0,b1)
    const int warp = threadIdx.x >> 5;
    const int lane = threadIdx.x & 31;
    float* xb = smem + GM_WF_FLOATS + warp * (2 * GM_BUF);
    const uint32_t xb_s = (uint32_t)__cvta_generic_to_shared(xb);

    // pack W1 into tf32 B fragments: b0 = B[k, n], b1 = B[k+4, n]
    for (int i = threadIdx.x; i < 64 * 2 * 32; i += GM_THREADS) {
        int li = i & 31, tile = (i >> 5) & 1, ks = i >> 6;
        int k = ks * 8 + (li & 3);
        int ncol = tile * 8 + (li >> 2);
        uint32_t b0 = f2tf32(__ldg(W1 + k * HID + ncol));
        uint32_t b1 = f2tf32(__ldg(W1 + (k + 4) * HID + ncol));
        Wf[i] = make_float2(__uint_as_float(b0), __uint_as_float(b1));
    }
    __syncthreads();

    const int nodebase = blockIdx.x * GM_TILE + warp * GM_NPW;
    const int row0 = lane >> 2, row1 = row0 + 8;
    const int k0 = lane & 3;

    // staging: 128 float4 per chunk (16 rows x 8 slots), 4 per lane
    uint32_t st_dst[4];
    const float4* st_src[4];
#pragma unroll
    for (int t = 0; t < 4; t++) {
        int idx = t * 32 + lane;            // 0..127
        int r = idx >> 3, c4 = idx & 7;
        st_dst[t] = xb_s + 16u * (r * 8 + (c4 ^ (r & 7)));
        int nd = nodebase + r;
        st_src[t] = (const float4*)x + ((nd < n) ? (size_t)nd * (IN_CH / 4) : 0) + c4;
    }

    float acc[8];                            // tile0: 0-3, tile1: 4-7
#pragma unroll
    for (int j = 0; j < 8; j++) acc[j] = 0.f;

    // prefetch chunk 0 into buffer 0
#pragma unroll
    for (int t = 0; t < 4; t++) cp_async16(st_dst[t], st_src[t]);
    asm volatile("cp.async.commit_group;" ::: "memory");

    const int aoff0 = row0 * GM_KC;
    const int aoff1 = row1 * GM_KC;
    const int rs0 = row0 & 7;                // == row1 & 7

    for (int c = 0; c < GM_NCHUNK; c++) {
        if (c + 1 < GM_NCHUNK) {
            const uint32_t nb_off = ((c + 1) & 1) * (GM_BUF * 4u);   // bytes: 0 or 2048
#pragma unroll
            for (int t = 0; t < 4; t++)
                cp_async16(st_dst[t] + nb_off, st_src[t] + (c + 1) * (GM_KC / 4));
            asm volatile("cp.async.commit_group;" ::: "memory");
            asm volatile("cp.async.wait_group 1;" ::: "memory");
        } else {
            asm volatile("cp.async.wait_group 0;" ::: "memory");
        }
        __syncwarp();

        const float* xc = xb + (c & 1) * GM_BUF;
#pragma unroll
        for (int ks = 0; ks < 4; ks++) {
            const int c4a = 2 * ks, c4b = 2 * ks + 1;
            uint32_t a0 = f2tf32(xc[aoff0 + ((c4a ^ rs0) << 2) + k0]);
            uint32_t a1 = f2tf32(xc[aoff1 + ((c4a ^ rs0) << 2) + k0]);
            uint32_t a2 = f2tf32(xc[aoff0 + ((c4b ^ rs0) << 2) + k0]);
            uint32_t a3 = f2tf32(xc[aoff1 + ((c4b ^ rs0) << 2) + k0]);
            const int ksg = c * 4 + ks;
            float2 bA = Wf[(ksg * 2 + 0) * 32 + lane];
            float2 bB = Wf[(ksg * 2 + 1) * 32 + lane];
            mma_tf32(acc,     a0, a1, a2, a3,
                     __float_as_uint(bA.x), __float_as_uint(bA.y));
            mma_tf32(acc + 4, a0, a1, a2, a3,
                     __float_as_uint(bB.x), __float_as_uint(bB.y));
        }
        __syncwarp();
    }

    // epilogue: fp8 stores. c0=(row, 2k0), c1=(row, 2k0+1), c2=(row+8, ..), c3=(row+8, ..)
    const int node0 = nodebase + row0;
    const int node1 = nodebase + row1;
    if (node0 < n) {
        float dv = __ldg(g_dinv + node0);
        uint16_t p0 = f2_to_e4m3x2(acc[0] * dv, acc[1] * dv);
        uint16_t p1 = f2_to_e4m3x2(acc[4] * dv, acc[5] * dv);
        *(uint16_t*)(g_h1q + (size_t)node0 * HID + 2 * k0)     = p0;
        *(uint16_t*)(g_h1q + (size_t)node0 * HID + 8 + 2 * k0) = p1;
    }
    if (node1 < n) {
        float dv = __ldg(g_dinv + node1);
        uint16_t p0 = f2_to_e4m3x2(acc[2] * dv, acc[3] * dv);
        uint16_t p1 = f2_to_e4m3x2(acc[6] * dv, acc[7] * dv);
        *(uint16_t*)(g_h1q + (size_t)node1 * HID + 2 * k0)     = p0;
        *(uint16_t*)(g_h1q + (size_t)node1 * HID + 8 + 2 * k0) = p1;
    }
}

// ---------------------------------------------------------------- scatter (fp8 gather, fp16 reds)
// ONE thread per edge: gather 16B = all 16 e4m3 channels (1 L1tex wavefront),
// convert to half2, scale by w, TWO red.v4.f16x2. 3 wavefronts/edge vs 4.
template <int LAYER>
__global__ void scatter_kernel(const int* __restrict__ ei1, const float* __restrict__ w1, int E1,
                               const int* __restrict__ ei2, const float* __restrict__ w2, int E2) {
    int e = blockIdx.x * blockDim.x + threadIdx.x;
    int row, col;
    float w;
    if (e < E1) {
        row = __ldg(ei1 + e); col = __ldg(ei1 + E1 + e); w = __ldg(w1 + e);
    } else {
        int j = e - E1;
        if (j >= E2) return;
        row = __ldg(ei2 + j); col = __ldg(ei2 + E2 + j); w = __ldg(w2 + j);
    }

    const uint8_t* src = (LAYER == 1) ? g_h1q : g_zq;
    __half*        dst = (LAYER == 1) ? g_agg1h : g_agg2h;

    uint4 q = __ldg((const uint4*)(src + (size_t)col * HID));
    __half2 w2h = __float2half2_rn(w);
    __half2 v0 = __hmul2(e4m3x2_to_h2((uint16_t)q.x),         w2h);
    __half2 v1 = __hmul2(e4m3x2_to_h2((uint16_t)(q.x >> 16)), w2h);
    __half2 v2 = __hmul2(e4m3x2_to_h2((uint16_t)q.y),         w2h);
    __half2 v3 = __hmul2(e4m3x2_to_h2((uint16_t)(q.y >> 16)), w2h);
    __half2 v4 = __hmul2(e4m3x2_to_h2((uint16_t)q.z),         w2h);
    __half2 v5 = __hmul2(e4m3x2_to_h2((uint16_t)(q.z >> 16)), w2h);
    __half2 v6 = __hmul2(e4m3x2_to_h2((uint16_t)q.w),         w2h);
    __half2 v7 = __hmul2(e4m3x2_to_h2((uint16_t)(q.w >> 16)), w2h);

    __half* d = dst + (size_t)row * HID;
    red_add_v4h2(d,     *(uint32_t*)&v0, *(uint32_t*)&v1, *(uint32_t*)&v2, *(uint32_t*)&v3);
    red_add_v4h2(d + 8, *(uint32_t*)&v4, *(uint32_t*)&v5, *(uint32_t*)&v6, *(uint32_t*)&v7);
}

// ---------------------------------------------------------------- zq = e4m3(dinv.*relu(dinv.*agg1h + b1)); zero agg2h
// one thread per half-node (8 channels)
__global__ void relu_kernel(const float* __restrict__ b1, int n) {
    int i = blockIdx.x * blockDim.x + threadIdx.x;
    if (i >= 2 * n) return;
    int node = i >> 1, sub = i & 1;
    float dv = __ldg(g_dinv + node);
    uint4 u = ((const uint4*)(g_agg1h))[i];
    const float4* bb = (const float4*)(b1 + sub * 8);
    float4 b0 = __ldg(bb), b1v = __ldg(bb + 1);
    float2 f0 = __half22float2(*(__half2*)&u.x);
    float2 f1 = __half22float2(*(__half2*)&u.y);
    float2 f2 = __half22float2(*(__half2*)&u.z);
    float2 f3 = __half22float2(*(__half2*)&u.w);
    f0.x = dv * fmaxf(dv * f0.x + b0.x, 0.f);  f0.y = dv * fmaxf(dv * f0.y + b0.y, 0.f);
    f1.x = dv * fmaxf(dv * f1.x + b0.z, 0.f);  f1.y = dv * fmaxf(dv * f1.y + b0.w, 0.f);
    f2.x = dv * fmaxf(dv * f2.x + b1v.x, 0.f); f2.y = dv * fmaxf(dv * f2.y + b1v.y, 0.f);
    f3.x = dv * fmaxf(dv * f3.x + b1v.z, 0.f); f3.y = dv * fmaxf(dv * f3.y + b1v.w, 0.f);
    uint32_t lo = ((uint32_t)f2_to_e4m3x2(f1.x, f1.y) << 16) | f2_to_e4m3x2(f0.x, f0.y);
    uint32_t hi = ((uint32_t)f2_to_e4m3x2(f3.x, f3.y) << 16) | f2_to_e4m3x2(f2.x, f2.y);
    ((uint2*)g_zq)[i] = make_uint2(lo, hi);
    ((uint4*)g_agg2h)[i] = make_uint4(0u, 0u, 0u, 0u);
}

// ---------------------------------------------------------------- out = log_softmax((dinv.*agg2h) @ W2 + b2)
#define OUT_WARPS 8
__global__ void out_kernel(const float* __restrict__ W2, const float* __restrict__ b2,
                           float* __restrict__ out, int n) {
    __shared__ float W2s[HID * OUT_CH];
    for (int t = threadIdx.x; t < HID * OUT_CH / 4; t += blockDim.x)
        ((float4*)W2s)[t] = ((const float4*)W2)[t];
    __syncthreads();

    int warp = threadIdx.x >> 5, lane = threadIdx.x & 31;
    int node = blockIdx.x * OUT_WARPS + warp;
    if (node >= n) return;

    float dv = __ldg(g_dinv + node);
    const uint4* a4 = (const uint4*)(g_agg2h + (size_t)node * HID);
    uint4 u0 = __ldg(a4), u1 = __ldg(a4 + 1);
    float a[16];
    {
        float2 f;
        f = __half22float2(*(__half2*)&u0.x); a[0]  = f.x; a[1]  = f.y;
        f = __half22float2(*(__half2*)&u0.y); a[2]  = f.x; a[3]  = f.y;
        f = __half22float2(*(__half2*)&u0.z); a[4]  = f.x; a[5]  = f.y;
        f = __half22float2(*(__half2*)&u0.w); a[6]  = f.x; a[7]  = f.y;
        f = __half22float2(*(__half2*)&u1.x); a[8]  = f.x; a[9]  = f.y;
        f = __half22float2(*(__half2*)&u1.y); a[10] = f.x; a[11] = f.y;
        f = __half22float2(*(__half2*)&u1.z); a[12] = f.x; a[13] = f.y;
        f = __half22float2(*(__half2*)&u1.w); a[14] = f.x; a[15] = f.y;
    }
#pragma unroll
    for (int k = 0; k < HID; k++) a[k] *= dv;

    float acc0 = b2[lane];
    float acc1 = b2[lane + 32];
#pragma unroll
    for (int k = 0; k < HID; k++) {
        acc0 += a[k] * W2s[k * OUT_CH + lane];
        acc1 += a[k] * W2s[k * OUT_CH + lane + 32];
    }

    float m = fmaxf(acc0, acc1);
#pragma unroll
    for (int off = 16; off >= 1; off >>= 1)
        m = fmaxf(m, __shfl_xor_sync(0xffffffffu, m, off));
    float s = expf(acc0 - m) + expf(acc1 - m);
#pragma unroll
    for (int off = 16; off >= 1; off >>= 1)
        s += __shfl_xor_sync(0xffffffffu, s, off);
    float lse = m + logf(s);

    out[(size_t)node * OUT_CH + lane]      = acc0 - lse;
    out[(size_t)node * OUT_CH + lane + 32] = acc1 - lse;
}

// ---------------------------------------------------------------- launch (serial champion order)
extern "C" void kernel_launch(void* const* d_in, const int* in_sizes, int n_in,
                              void* d_out, int out_size) {
    const float* x   = (const float*)d_in[0];
    const int*   ei1 = (const int*)  d_in[1];
    const float* ew1 = (const float*)d_in[2];
    const int*   ei2 = (const int*)  d_in[3];
    const float* ew2 = (const float*)d_in[4];
    const float* W1  = (const float*)d_in[5];
    const float* b1  = (const float*)d_in[6];
    const float* W2  = (const float*)d_in[7];
    const float* b2  = (const float*)d_in[8];
    float* out = (float*)d_out;

    int n  = in_sizes[0] / IN_CH;
    int E1 = in_sizes[2];
    int E2 = in_sizes[4];
    int Et = E1 + E2;

    const int GM_SMEM = GM_SMEM_FLOATS * (int)sizeof(float);
    cudaFuncSetAttribute(gemm1_kernel, cudaFuncAttributeMaxDynamicSharedMemorySize, GM_SMEM);

    zero_kernel<<<(n * HID / 8 + 255) / 256, 256>>>(n);
    deg_kernel<<<(Et + 255) / 256, 256>>>(ei1, ew1, E1, ei2, ew2, E2);
    dinv_kernel<<<(n + 255) / 256, 256>>>(n);
    gemm1_kernel<<<(n + GM_TILE - 1) / GM_TILE, GM_THREADS, GM_SMEM>>>(x, W1, n);
    scatter_kernel<1><<<(Et + 255) / 256, 256>>>(ei1, ew1, E1, ei2, ew2, E2);
    relu_kernel<<<(2 * n + 255) / 256, 256>>>(b1, n);
    scatter_kernel<2><<<(Et + 255) / 256, 256>>>(ei1, ew1, E1, ei2, ew2, E2);
    out_kernel<<<(n + OUT_WARPS - 1) / OUT_WARPS, OUT_WARPS * 32>>>(W2, b2, out, n);
}

// round 17
// speedup vs baseline: 1.0101x; 1.0101x over previous
#include <cuda_runtime.h>
#include <cuda_fp16.h>
#include <cstdint>

#define IN_CH  512
#define HID    16
#define OUT_CH 64
#define MAX_NODES 100352
#define MAX_EDGES 3276800

// ---- scratch (device globals; no allocation allowed) ----
__device__ float  g_deg  [MAX_NODES];
__device__ float  g_dinv [MAX_NODES];
__device__ __half g_h1h  [MAX_NODES * HID];  // fp16 dinv-prescaled x@W1 (3.2MB, L2-resident)
__device__ __half g_zh   [MAX_NODES * HID];  // fp16 dinv*relu(dinv*agg1+b1)
__device__ __half g_agg1h[MAX_NODES * HID];  // fp16 accumulation buffers
__device__ __half g_agg2h[MAX_NODES * HID];
__device__ float2 g_Wf   [64 * 2 * 32];      // W1 tf32 B-fragments (32KB, L1-resident)

// 128-bit fp16x2 reduction: 8 halves in ONE red-lane-op (the scatter currency)
__device__ __forceinline__ void red_add_v4h2(__half* p, uint32_t r0, uint32_t r1,
                                             uint32_t r2, uint32_t r3) {
    asm volatile("red.global.add.noftz.v4.f16x2 [%0], {%1,%2,%3,%4};"
                 :: "l"(p), "r"(r0), "r"(r1), "r"(r2), "r"(r3) : "memory");
}

__device__ __forceinline__ void cp_async16(uint32_t dst, const void* src) {
    asm volatile("cp.async.cg.shared.global [%0], [%1], 16;" :: "r"(dst), "l"(src));
}

__device__ __forceinline__ uint32_t f2tf32(float f) {
    uint32_t r;
    asm("cvt.rna.tf32.f32 %0, %1;" : "=r"(r) : "f"(f));
    return r;
}

// D += A(16x8) * B(8x8), tf32 inputs, fp32 accum
__device__ __forceinline__ void mma_tf32(float* c, uint32_t a0, uint32_t a1,
                                         uint32_t a2, uint32_t a3,
                                         uint32_t b0, uint32_t b1) {
    asm volatile("mma.sync.aligned.m16n8k8.row.col.f32.tf32.tf32.f32 "
                 "{%0,%1,%2,%3}, {%4,%5,%6,%7}, {%8,%9}, {%0,%1,%2,%3};"
                 : "+f"(c[0]), "+f"(c[1]), "+f"(c[2]), "+f"(c[3])
                 : "r"(a0), "r"(a1), "r"(a2), "r"(a3), "r"(b0), "r"(b1));
}

// ---------------------------------------------------------------- pack W1 into tf32 B fragments (once)
// layout: g_Wf[(ks*2 + tile)*32 + lane] = (B[k,n], B[k+4,n]) with k=ks*8+(lane&3),
// n=tile*8+(lane>>2) — exact m16n8k8 tf32 B-fragment order.
__global__ void pack_w_kernel(const float* __restrict__ W1) {
    int i = blockIdx.x * blockDim.x + threadIdx.x;
    if (i >= 64 * 2 * 32) return;
    int li = i & 31, tile = (i >> 5) & 1, ks = i >> 6;
    int k = ks * 8 + (li & 3);
    int ncol = tile * 8 + (li >> 2);
    uint32_t b0 = f2tf32(__ldg(W1 + k * HID + ncol));
    uint32_t b1 = f2tf32(__ldg(W1 + (k + 4) * HID + ncol));
    g_Wf[i] = make_float2(__uint_as_float(b0), __uint_as_float(b1));
}

// ---------------------------------------------------------------- zero (agg1h + deg)
__global__ void zero_kernel(int n) {
    int i = blockIdx.x * blockDim.x + threadIdx.x;
    int t4 = n * HID / 8;            // uint4 = 8 halves
    if (i < t4) ((uint4*)g_agg1h)[i] = make_uint4(0u, 0u, 0u, 0u);
    if (i < n) g_deg[i] = 0.f;
}

// ---------------------------------------------------------------- degree
__global__ void deg_kernel(const int* __restrict__ ei1, const float* __restrict__ w1, int E1,
                           const int* __restrict__ ei2, const float* __restrict__ w2, int E2) {
    int i = blockIdx.x * blockDim.x + threadIdx.x;
    if (i < E1) {
        atomicAdd(&g_deg[ei1[i]], w1[i]);
    } else {
        int j = i - E1;
        if (j < E2) atomicAdd(&g_deg[ei2[j]], w2[j]);
    }
}

__global__ void dinv_kernel(int n) {
    int i = blockIdx.x * blockDim.x + threadIdx.x;
    if (i >= n) return;
    float d = g_deg[i];
    g_dinv[i] = d > 0.f ? rsqrtf(fmaxf(d, 1e-12f)) : 0.f;
}

// ---------------------------------------------------------------- h1h = fp16(dinv .* (x @ W1))  [tf32 tensor cores]
// R13 shape (warp = 16 nodes, 2 mma n-tiles, KC=32, cp.async double buffer),
// but W fragments moved to a global L1-resident table -> smem = 32KB x-buffers
// only -> 4 blocks/SM (32 warps) with per-chunk work UNCHANGED (R14 lesson).
#define GM_THREADS 256
#define GM_WARPS   8
#define GM_NPW     16
#define GM_TILE    (GM_WARPS * GM_NPW)      // 128 nodes per block
#define GM_KC      32                       // floats per chunk
#define GM_NCHUNK  (IN_CH / GM_KC)          // 16
#define GM_BUF     (GM_NPW * GM_KC)         // 512 floats per buffer (2048 bytes)
#define GM_SMEM_FLOATS (GM_WARPS * 2 * GM_BUF)   // 8192 floats = 32KB

__global__ void __launch_bounds__(GM_THREADS, 4)
gemm1_kernel(const float* __restrict__ x, int n) {
    extern __shared__ float smem[];
    const int warp = threadIdx.x >> 5;
    const int lane = threadIdx.x & 31;
    float* xb = smem + warp * (2 * GM_BUF);
    const uint32_t xb_s = (uint32_t)__cvta_generic_to_shared(xb);

    const int nodebase = blockIdx.x * GM_TILE + warp * GM_NPW;
    const int row0 = lane >> 2, row1 = row0 + 8;
    const int k0 = lane & 3;

    // staging: 128 float4 per chunk (16 rows x 8 slots), 4 per lane
    uint32_t st_dst[4];
    const float4* st_src[4];
#pragma unroll
    for (int t = 0; t < 4; t++) {
        int idx = t * 32 + lane;            // 0..127
        int r = idx >> 3, c4 = idx & 7;
        st_dst[t] = xb_s + 16u * (r * 8 + (c4 ^ (r & 7)));
        int nd = nodebase + r;
        st_src[t] = (const float4*)x + ((nd < n) ? (size_t)nd * (IN_CH / 4) : 0) + c4;
    }

    float acc[8];                            // tile0: 0-3, tile1: 4-7
#pragma unroll
    for (int j = 0; j < 8; j++) acc[j] = 0.f;

    // prefetch chunk 0 into buffer 0
#pragma unroll
    for (int t = 0; t < 4; t++) cp_async16(st_dst[t], st_src[t]);
    asm volatile("cp.async.commit_group;" ::: "memory");

    const int aoff0 = row0 * GM_KC;
    const int aoff1 = row1 * GM_KC;
    const int rs0 = row0 & 7;                // == row1 & 7
    const float2* wf_lane = g_Wf + lane;

    for (int c = 0; c < GM_NCHUNK; c++) {
        if (c + 1 < GM_NCHUNK) {
            const uint32_t nb_off = ((c + 1) & 1) * (GM_BUF * 4u);   // bytes: 0 or 2048
#pragma unroll
            for (int t = 0; t < 4; t++)
                cp_async16(st_dst[t] + nb_off, st_src[t] + (c + 1) * (GM_KC / 4));
            asm volatile("cp.async.commit_group;" ::: "memory");
            asm volatile("cp.async.wait_group 1;" ::: "memory");
        } else {
            asm volatile("cp.async.wait_group 0;" ::: "memory");
        }
        __syncwarp();

        const float* xc = xb + (c & 1) * GM_BUF;
#pragma unroll
        for (int ks = 0; ks < 4; ks++) {
            const int c4a = 2 * ks, c4b = 2 * ks + 1;
            // A fragment: a0=(row0,k), a1=(row1,k), a2=(row0,k+4), a3=(row1,k+4)
            uint32_t a0 = f2tf32(xc[aoff0 + ((c4a ^ rs0) << 2) + k0]);
            uint32_t a1 = f2tf32(xc[aoff1 + ((c4a ^ rs0) << 2) + k0]);
            uint32_t a2 = f2tf32(xc[aoff0 + ((c4b ^ rs0) << 2) + k0]);
            uint32_t a3 = f2tf32(xc[aoff1 + ((c4b ^ rs0) << 2) + k0]);
            const int ksg = c * 4 + ks;
            float2 bA = __ldg(wf_lane + (ksg * 2 + 0) * 32);
            float2 bB = __ldg(wf_lane + (ksg * 2 + 1) * 32);
            mma_tf32(acc,     a0, a1, a2, a3,
                     __float_as_uint(bA.x), __float_as_uint(bA.y));
            mma_tf32(acc + 4, a0, a1, a2, a3,
                     __float_as_uint(bB.x), __float_as_uint(bB.y));
        }
        __syncwarp();
    }

    // epilogue: C layout c0=(row, 2k0), c1=(row, 2k0+1), c2=(row+8, 2k0), c3=(row+8, 2k0+1)
    const int node0 = nodebase + row0;
    const int node1 = nodebase + row1;
    if (node0 < n) {
        float dv = __ldg(g_dinv + node0);
        __half2 t0 = __floats2half2_rn(acc[0] * dv, acc[1] * dv);
        __half2 t1 = __floats2half2_rn(acc[4] * dv, acc[5] * dv);
        *(uint32_t*)(g_h1h + (size_t)node0 * HID + 2 * k0)     = *(uint32_t*)&t0;
        *(uint32_t*)(g_h1h + (size_t)node0 * HID + 8 + 2 * k0) = *(uint32_t*)&t1;
    }
    if (node1 < n) {
        float dv = __ldg(g_dinv + node1);
        __half2 t0 = __floats2half2_rn(acc[2] * dv, acc[3] * dv);
        __half2 t1 = __floats2half2_rn(acc[6] * dv, acc[7] * dv);
        *(uint32_t*)(g_h1h + (size_t)node1 * HID + 2 * k0)     = *(uint32_t*)&t0;
        *(uint32_t*)(g_h1h + (size_t)node1 * HID + 8 + 2 * k0) = *(uint32_t*)&t1;
    }
}

// ---------------------------------------------------------------- scatter (fp16 reds, R13 champion)
// 2 lanes per edge: gather 16B (8 halves), scale by w, ONE red.v4.f16x2.
// RED path at L2 is the measured floor (fp8 gather test changed nothing).
template <int LAYER>
__global__ void scatter_kernel(const int* __restrict__ ei1, const float* __restrict__ w1, int E1,
                               const int* __restrict__ ei2, const float* __restrict__ w2, int E2) {
    int t = blockIdx.x * blockDim.x + threadIdx.x;
    int e   = t >> 1;
    int sub = t & 1;
    int row, col;
    float w;
    if (e < E1) {
        row = __ldg(ei1 + e); col = __ldg(ei1 + E1 + e); w = __ldg(w1 + e);
    } else {
        int j = e - E1;
        if (j >= E2) return;
        row = __ldg(ei2 + j); col = __ldg(ei2 + E2 + j); w = __ldg(w2 + j);
    }

    const __half* src = (LAYER == 1) ? g_h1h : g_zh;
    __half*       dst = (LAYER == 1) ? g_agg1h : g_agg2h;

    uint4 hv = __ldg((const uint4*)(src + (size_t)col * HID + sub * 8));
    __half2 w2h = __float2half2_rn(w);
    __half2 h0 = __hmul2(*(__half2*)&hv.x, w2h);
    __half2 h1 = __hmul2(*(__half2*)&hv.y, w2h);
    __half2 h2 = __hmul2(*(__half2*)&hv.z, w2h);
    __half2 h3 = __hmul2(*(__half2*)&hv.w, w2h);

    red_add_v4h2(dst + (size_t)row * HID + sub * 8,
                 *(uint32_t*)&h0, *(uint32_t*)&h1, *(uint32_t*)&h2, *(uint32_t*)&h3);
}

// ---------------------------------------------------------------- zh = fp16(dinv.*relu(dinv.*agg1h + b1)); zero agg2h
__global__ void relu_kernel(const float* __restrict__ b1, int n) {
    int i = blockIdx.x * blockDim.x + threadIdx.x;
    if (i >= 2 * n) return;
    int node = i >> 1, sub = i & 1;
    float dv = __ldg(g_dinv + node);
    uint4 u = ((const uint4*)(g_agg1h))[i];
    const float4* bb = (const float4*)(b1 + sub * 8);
    float4 b0 = __ldg(bb), b1v = __ldg(bb + 1);
    float2 f0 = __half22float2(*(__half2*)&u.x);
    float2 f1 = __half22float2(*(__half2*)&u.y);
    float2 f2 = __half22float2(*(__half2*)&u.z);
    float2 f3 = __half22float2(*(__half2*)&u.w);
    f0.x = dv * fmaxf(dv * f0.x + b0.x, 0.f);  f0.y = dv * fmaxf(dv * f0.y + b0.y, 0.f);
    f1.x = dv * fmaxf(dv * f1.x + b0.z, 0.f);  f1.y = dv * fmaxf(dv * f1.y + b0.w, 0.f);
    f2.x = dv * fmaxf(dv * f2.x + b1v.x, 0.f); f2.y = dv * fmaxf(dv * f2.y + b1v.y, 0.f);
    f3.x = dv * fmaxf(dv * f3.x + b1v.z, 0.f); f3.y = dv * fmaxf(dv * f3.y + b1v.w, 0.f);
    __half2 h0 = __floats2half2_rn(f0.x, f0.y);
    __half2 h1 = __floats2half2_rn(f1.x, f1.y);
    __half2 h2 = __floats2half2_rn(f2.x, f2.y);
    __half2 h3 = __floats2half2_rn(f3.x, f3.y);
    ((uint4*)g_zh)[i] = make_uint4(*(unsigned*)&h0, *(unsigned*)&h1,
                                   *(unsigned*)&h2, *(unsigned*)&h3);
    ((uint4*)g_agg2h)[i] = make_uint4(0u, 0u, 0u, 0u);
}

// ---------------------------------------------------------------- out = log_softmax((dinv.*agg2h) @ W2 + b2)
#define OUT_WARPS 8
__global__ void out_kernel(const float* __restrict__ W2, const float* __restrict__ b2,
                           float* __restrict__ out, int n) {
    __shared__ float W2s[HID * OUT_CH];
    for (int t = threadIdx.x; t < HID * OUT_CH / 4; t += blockDim.x)
        ((float4*)W2s)[t] = ((const float4*)W2)[t];
    __syncthreads();

    int warp = threadIdx.x >> 5, lane = threadIdx.x & 31;
    int node = blockIdx.x * OUT_WARPS + warp;
    if (node >= n) return;

    float dv = __ldg(g_dinv + node);
    const uint4* a4 = (const uint4*)(g_agg2h + (size_t)node * HID);
    uint4 u0 = __ldg(a4), u1 = __ldg(a4 + 1);
    float a[16];
    {
        float2 f;
        f = __half22float2(*(__half2*)&u0.x); a[0]  = f.x; a[1]  = f.y;
        f = __half22float2(*(__half2*)&u0.y); a[2]  = f.x; a[3]  = f.y;
        f = __half22float2(*(__half2*)&u0.z); a[4]  = f.x; a[5]  = f.y;
        f = __half22float2(*(__half2*)&u0.w); a[6]  = f.x; a[7]  = f.y;
        f = __half22float2(*(__half2*)&u1.x); a[8]  = f.x; a[9]  = f.y;
        f = __half22float2(*(__half2*)&u1.y); a[10] = f.x; a[11] = f.y;
        f = __half22float2(*(__half2*)&u1.z); a[12] = f.x; a[13] = f.y;
        f = __half22float2(*(__half2*)&u1.w); a[14] = f.x; a[15] = f.y;
    }
#pragma unroll
    for (int k = 0; k < HID; k++) a[k] *= dv;

    float acc0 = b2[lane];
    float acc1 = b2[lane + 32];
#pragma unroll
    for (int k = 0; k < HID; k++) {
        acc0 += a[k] * W2s[k * OUT_CH + lane];
        acc1 += a[k] * W2s[k * OUT_CH + lane + 32];
    }

    float m = fmaxf(acc0, acc1);
#pragma unroll
    for (int off = 16; off >= 1; off >>= 1)
        m = fmaxf(m, __shfl_xor_sync(0xffffffffu, m, off));
    float s = expf(acc0 - m) + expf(acc1 - m);
#pragma unroll
    for (int off = 16; off >= 1; off >>= 1)
        s += __shfl_xor_sync(0xffffffffu, s, off);
    float lse = m + logf(s);

    out[(size_t)node * OUT_CH + lane]      = acc0 - lse;
    out[(size_t)node * OUT_CH + lane + 32] = acc1 - lse;
}

// ---------------------------------------------------------------- launch
extern "C" void kernel_launch(void* const* d_in, const int* in_sizes, int n_in,
                              void* d_out, int out_size) {
    const float* x   = (const float*)d_in[0];
    const int*   ei1 = (const int*)  d_in[1];
    const float* ew1 = (const float*)d_in[2];
    const int*   ei2 = (const int*)  d_in[3];
    const float* ew2 = (const float*)d_in[4];
    const float* W1  = (const float*)d_in[5];
    const float* b1  = (const float*)d_in[6];
    const float* W2  = (const float*)d_in[7];
    const float* b2  = (const float*)d_in[8];
    float* out = (float*)d_out;

    int n  = in_sizes[0] / IN_CH;
    int E1 = in_sizes[2];
    int E2 = in_sizes[4];
    int Et = E1 + E2;

    const int GM_SMEM = GM_SMEM_FLOATS * (int)sizeof(float);
    cudaFuncSetAttribute(gemm1_kernel, cudaFuncAttributeMaxDynamicSharedMemorySize, GM_SMEM);

    pack_w_kernel<<<(64 * 2 * 32 + 255) / 256, 256>>>(W1);
    zero_kernel<<<(n * HID / 8 + 255) / 256, 256>>>(n);
    deg_kernel<<<(Et + 255) / 256, 256>>>(ei1, ew1, E1, ei2, ew2, E2);
    dinv_kernel<<<(n + 255) / 256, 256>>>(n);
    gemm1_kernel<<<(n + GM_TILE - 1) / GM_TILE, GM_THREADS, GM_SMEM>>>(x, n);
    scatter_kernel<1><<<(2 * Et + 255) / 256, 256>>>(ei1, ew1, E1, ei2, ew2, E2);
    relu_kernel<<<(2 * n + 255) / 256, 256>>>(b1, n);
    scatter_kernel<2><<<(2 * Et + 255) / 256, 256>>>(ei1, ew1, E1, ei2, ew2, E2);
    out_kernel<<<(n + OUT_WARPS - 1) / OUT_WARPS, OUT_WARPS * 32>>>(W2, b2, out, n);
}